// round 2
// baseline (speedup 1.0000x reference)
#include <cuda_runtime.h>
#include <cstdint>

// ---------------- problem constants ----------------
#define NB    32
#define NC    64
#define HW    56
#define OHW   57
#define LL    3249           // 57*57
#define PP    256            // C*ks*ks
#define NROWS 103968         // NB*LL  (flat rows, 256 elems each)
#define KCL   512            // clusters
#define PLSZ  831744         // PP*LL

// ---------------- scratch (device globals; no allocs allowed) ----------------
__device__ float g_cols [26615808];   // [NB][PP][LL]  == flat [NROWS][256]
__device__ float g_final[26615808];   // masked final, same layout
__device__ float g_S    [53231616];   // [NROWS][512] scores -> softmax weights (in place)
__device__ float g_x2   [NROWS];
__device__ float g_c2   [KCL];

// ---------------- fast math (avoid MUFU pipe) ----------------
__device__ __forceinline__ float fast_sqrtf(float q) {
    // rsqrt bit hack + 3 Newton steps: rel err ~1e-9, no MUFU
    float r = __int_as_float(0x5f3759df - (__float_as_int(q) >> 1));
    r = r * fmaf(-0.5f * q, r * r, 1.5f);
    r = r * fmaf(-0.5f * q, r * r, 1.5f);
    r = r * fmaf(-0.5f * q, r * r, 1.5f);
    float s = q * r;
    return (q > 1e-20f) ? s : 0.0f;
}

__device__ __forceinline__ float fast_expf(float x) {
    // x <= 0 expected. exp(x) = 2^(x*log2e); magic-number round, degree-5 poly, exponent splice.
    x = fmaxf(x, -80.0f);
    float y  = x * 1.44269504088896f;
    float t  = y + 12582912.0f;                      // round to nearest int in mantissa
    float nf = t - 12582912.0f;
    float f  = y - nf;                               // f in [-0.5, 0.5]
    int   e  = (__float_as_int(t) & 0x7FFFFF) - 0x400000;
    float p  = 1.3333558146e-3f;
    p = fmaf(p, f, 9.6180905e-3f);
    p = fmaf(p, f, 5.5504108665e-2f);
    p = fmaf(p, f, 2.4022650696e-1f);
    p = fmaf(p, f, 6.9314718056e-1f);
    p = fmaf(p, f, 1.0f);
    return p * __int_as_float((e + 127) << 23);
}

// ---------------- kernel 1: unfold + fused row |x|^2 ----------------
// one block (256 thr) == one flat row (256 contiguous [B,P,L]-linear elements).
// NOTE: L=3249 is NOT a multiple of 256, so a "flat row" straddles (p,l) —
// decompose the LINEAR index g, never assume one row == one patch.
__global__ void k_unfold(const float* __restrict__ x) {
    unsigned n = blockIdx.x;
    unsigned g = n * 256u + threadIdx.x;
    unsigned b   = g / PLSZ;
    unsigned rem = g - b * PLSZ;
    unsigned p   = rem / LL;
    unsigned l   = rem - p * LL;
    unsigned c  = p >> 2, ki = (p >> 1) & 1u, kj = p & 1u;
    unsigned oi = l / OHW, oj = l - oi * OHW;
    int r  = (int)(oi + ki) - 1;
    int cc = (int)(oj + kj) - 1;
    float v = 0.0f;
    if ((unsigned)r < HW && (unsigned)cc < HW)
        v = x[(((b * NC + c) * HW + (unsigned)r) * HW + (unsigned)cc)];
    g_cols[g] = v;

    float s = v * v;
    #pragma unroll
    for (int o = 16; o; o >>= 1) s += __shfl_xor_sync(0xffffffffu, s, o);
    __shared__ float ws[8];
    if ((threadIdx.x & 31) == 0) ws[threadIdx.x >> 5] = s;
    __syncthreads();
    if (threadIdx.x < 8) {
        float tsum = ws[threadIdx.x];
        #pragma unroll
        for (int o = 4; o; o >>= 1) tsum += __shfl_xor_sync(0xffu, tsum, o);
        if (threadIdx.x == 0) g_x2[n] = tsum;
    }
}

// ---------------- kernel 2: |c|^2 per center ----------------
__global__ void k_c2(const float* __restrict__ cent) {
    int k = blockIdx.x * 8 + (threadIdx.x >> 5);
    int lane = threadIdx.x & 31;
    float s = 0.0f;
    #pragma unroll
    for (int i = 0; i < 8; i++) {
        float v = cent[k * 256 + lane + 32 * i];
        s = fmaf(v, v, s);
    }
    #pragma unroll
    for (int o = 16; o; o >>= 1) s += __shfl_xor_sync(0xffffffffu, s, o);
    if (lane == 0) g_c2[k] = s;
}

// ---------------- kernel 3: GEMM1 (NT)  S = flat @ C^T ----------------
// A = g_cols [NROWS][256] row-major, B = centers [512][256] row-major
__global__ __launch_bounds__(256, 2) void k_gemm1(const float* __restrict__ cent) {
    __shared__ __align__(16) float As[16][128];
    __shared__ __align__(16) float Bs[16][128];
    const int tid  = threadIdx.x;
    const int m0   = blockIdx.x * 128;
    const int n0   = blockIdx.y * 128;
    const int lrow = tid >> 2;
    const int lq   = (tid & 3) << 2;
    const int tx   = tid & 15, ty = tid >> 4;
    float acc[8][8];
    #pragma unroll
    for (int i = 0; i < 8; i++)
        #pragma unroll
        for (int j = 0; j < 8; j++) acc[i][j] = 0.0f;

    float4 a0, a1, b0, b1;
    const float4 z4 = make_float4(0.f, 0.f, 0.f, 0.f);
    // prologue load k0 = 0
    {
        int r0 = m0 + lrow, r1 = r0 + 64;
        a0 = (r0 < NROWS) ? *(const float4*)&g_cols[(size_t)r0 * 256 + lq] : z4;
        a1 = (r1 < NROWS) ? *(const float4*)&g_cols[(size_t)r1 * 256 + lq] : z4;
        b0 = *(const float4*)&cent[(n0 + lrow) * 256 + lq];
        b1 = *(const float4*)&cent[(n0 + lrow + 64) * 256 + lq];
    }
    for (int k0 = 0; k0 < 256; k0 += 16) {
        __syncthreads();
        As[lq + 0][lrow] = a0.x; As[lq + 1][lrow] = a0.y; As[lq + 2][lrow] = a0.z; As[lq + 3][lrow] = a0.w;
        As[lq + 0][lrow + 64] = a1.x; As[lq + 1][lrow + 64] = a1.y; As[lq + 2][lrow + 64] = a1.z; As[lq + 3][lrow + 64] = a1.w;
        Bs[lq + 0][lrow] = b0.x; Bs[lq + 1][lrow] = b0.y; Bs[lq + 2][lrow] = b0.z; Bs[lq + 3][lrow] = b0.w;
        Bs[lq + 0][lrow + 64] = b1.x; Bs[lq + 1][lrow + 64] = b1.y; Bs[lq + 2][lrow + 64] = b1.z; Bs[lq + 3][lrow + 64] = b1.w;
        __syncthreads();
        int kn = k0 + 16;
        if (kn < 256) {
            int r0 = m0 + lrow, r1 = r0 + 64;
            a0 = (r0 < NROWS) ? *(const float4*)&g_cols[(size_t)r0 * 256 + kn + lq] : z4;
            a1 = (r1 < NROWS) ? *(const float4*)&g_cols[(size_t)r1 * 256 + kn + lq] : z4;
            b0 = *(const float4*)&cent[(n0 + lrow) * 256 + kn + lq];
            b1 = *(const float4*)&cent[(n0 + lrow + 64) * 256 + kn + lq];
        }
        #pragma unroll
        for (int kk = 0; kk < 16; kk++) {
            float a[8], bf[8];
            *(float4*)(a)      = *(const float4*)&As[kk][ty * 8];
            *(float4*)(a + 4)  = *(const float4*)&As[kk][ty * 8 + 4];
            *(float4*)(bf)     = *(const float4*)&Bs[kk][tx * 8];
            *(float4*)(bf + 4) = *(const float4*)&Bs[kk][tx * 8 + 4];
            #pragma unroll
            for (int i = 0; i < 8; i++)
                #pragma unroll
                for (int j = 0; j < 8; j++)
                    acc[i][j] = fmaf(a[i], bf[j], acc[i][j]);
        }
    }
    #pragma unroll
    for (int i = 0; i < 8; i++) {
        int r = m0 + ty * 8 + i;
        if (r < NROWS) {
            float4 v0 = make_float4(acc[i][0], acc[i][1], acc[i][2], acc[i][3]);
            float4 v1 = make_float4(acc[i][4], acc[i][5], acc[i][6], acc[i][7]);
            *(float4*)&g_S[(size_t)r * 512 + n0 + tx * 8]     = v0;
            *(float4*)&g_S[(size_t)r * 512 + n0 + tx * 8 + 4] = v1;
        }
    }
}

// ---------------- kernel 4: softmax over 512 centers per row ----------------
__global__ void k_softmax(const float* __restrict__ temp_p) {
    __shared__ float c2s[KCL];
    for (int i = threadIdx.x; i < KCL; i += 256) c2s[i] = g_c2[i];
    __syncthreads();
    int n = blockIdx.x * 8 + (threadIdx.x >> 5);
    int lane = threadIdx.x & 31;
    float temp = *temp_p;
    float x2 = g_x2[n];
    float sc[16];
    float m = -1e30f;
    #pragma unroll
    for (int i = 0; i < 16; i++) {
        int k = lane + 32 * i;
        float s = g_S[(size_t)n * 512 + k];
        float q = fmaxf(fmaf(-2.0f, s, x2 + c2s[k]), 0.0f);
        sc[i] = -fast_sqrtf(q) * temp;
        m = fmaxf(m, sc[i]);
    }
    #pragma unroll
    for (int o = 16; o; o >>= 1) m = fmaxf(m, __shfl_xor_sync(0xffffffffu, m, o));
    float e[16];
    float sum = 0.0f;
    #pragma unroll
    for (int i = 0; i < 16; i++) { e[i] = fast_expf(sc[i] - m); sum += e[i]; }
    #pragma unroll
    for (int o = 16; o; o >>= 1) sum += __shfl_xor_sync(0xffffffffu, sum, o);
    float inv = 1.0f / sum;
    #pragma unroll
    for (int i = 0; i < 16; i++)
        g_S[(size_t)n * 512 + lane + 32 * i] = e[i] * inv;
}

// ---------------- kernel 5: GEMM2 (NN)  T = soft @ C, epilogue -> masked final ----------------
__global__ __launch_bounds__(256, 2) void k_gemm2(const float* __restrict__ cent,
                                                  const float* __restrict__ temp_p) {
    __shared__ __align__(16) float As[16][128];
    __shared__ __align__(16) float Bs[16][128];
    const int tid  = threadIdx.x;
    const int m0   = blockIdx.x * 128;
    const int j0   = blockIdx.y * 128;
    const int lrow = tid >> 2;
    const int lq   = (tid & 3) << 2;
    const int brow = tid >> 5;          // 0..7
    const int bcol = (tid & 31) << 2;   // 0..124
    const int tx   = tid & 15, ty = tid >> 4;
    float acc[8][8];
    #pragma unroll
    for (int i = 0; i < 8; i++)
        #pragma unroll
        for (int j = 0; j < 8; j++) acc[i][j] = 0.0f;

    float4 a0, a1, b0, b1;
    const float4 z4 = make_float4(0.f, 0.f, 0.f, 0.f);
    {
        int r0 = m0 + lrow, r1 = r0 + 64;
        a0 = (r0 < NROWS) ? *(const float4*)&g_S[(size_t)r0 * 512 + lq] : z4;
        a1 = (r1 < NROWS) ? *(const float4*)&g_S[(size_t)r1 * 512 + lq] : z4;
        b0 = *(const float4*)&cent[(brow) * 256 + j0 + bcol];
        b1 = *(const float4*)&cent[(brow + 8) * 256 + j0 + bcol];
    }
    for (int k0 = 0; k0 < 512; k0 += 16) {
        __syncthreads();
        As[lq + 0][lrow] = a0.x; As[lq + 1][lrow] = a0.y; As[lq + 2][lrow] = a0.z; As[lq + 3][lrow] = a0.w;
        As[lq + 0][lrow + 64] = a1.x; As[lq + 1][lrow + 64] = a1.y; As[lq + 2][lrow + 64] = a1.z; As[lq + 3][lrow + 64] = a1.w;
        *(float4*)&Bs[brow][bcol]     = b0;
        *(float4*)&Bs[brow + 8][bcol] = b1;
        __syncthreads();
        int kn = k0 + 16;
        if (kn < 512) {
            int r0 = m0 + lrow, r1 = r0 + 64;
            a0 = (r0 < NROWS) ? *(const float4*)&g_S[(size_t)r0 * 512 + kn + lq] : z4;
            a1 = (r1 < NROWS) ? *(const float4*)&g_S[(size_t)r1 * 512 + kn + lq] : z4;
            b0 = *(const float4*)&cent[(kn + brow) * 256 + j0 + bcol];
            b1 = *(const float4*)&cent[(kn + brow + 8) * 256 + j0 + bcol];
        }
        #pragma unroll
        for (int kk = 0; kk < 16; kk++) {
            float a[8], bf[8];
            *(float4*)(a)      = *(const float4*)&As[kk][ty * 8];
            *(float4*)(a + 4)  = *(const float4*)&As[kk][ty * 8 + 4];
            *(float4*)(bf)     = *(const float4*)&Bs[kk][tx * 8];
            *(float4*)(bf + 4) = *(const float4*)&Bs[kk][tx * 8 + 4];
            #pragma unroll
            for (int i = 0; i < 8; i++)
                #pragma unroll
                for (int j = 0; j < 8; j++)
                    acc[i][j] = fmaf(a[i], bf[j], acc[i][j]);
        }
    }
    // epilogue: final = (temp*T + flat)/(temp+1), with conv-boundary mask baked in
    float temp = *temp_p;
    float wT = temp / (temp + 1.0f);
    float wF = 1.0f / (temp + 1.0f);
    #pragma unroll
    for (int i = 0; i < 8; i++) {
        int r = m0 + ty * 8 + i;
        if (r >= NROWS) continue;
        #pragma unroll
        for (int j = 0; j < 8; j++) {
            unsigned g   = (unsigned)r * 256u + (unsigned)(j0 + tx * 8 + j);
            unsigned rem = g % PLSZ;
            unsigned p   = rem / LL;
            unsigned l   = rem - p * LL;
            unsigned ki  = (p >> 1) & 1u, kj = p & 1u;
            unsigned lm  = l % OHW;
            bool masked = (ki == 0u && l < OHW) || (ki == 1u && l >= 3192u) ||
                          (kj == 0u && lm == 0u) || (kj == 1u && lm == 56u);
            float val = masked ? 0.0f : fmaf(wT, acc[i][j], wF * g_cols[g]);
            g_final[g] = val;
        }
    }
}

// ---------------- kernel 6: GEMM3 (collapsed fold+conv)  out_b = Wf @ final_b + bias ----------------
__global__ __launch_bounds__(256, 2) void k_gemm3(const float* __restrict__ w,
                                                  const float* __restrict__ bias,
                                                  float* __restrict__ out) {
    __shared__ __align__(16) float As[16][128];
    __shared__ __align__(16) float Bs[16][128];
    const int tid  = threadIdx.x;
    const int bb   = blockIdx.y;        // batch
    const int l0   = blockIdx.x * 128;  // l tile
    const int lrow = tid >> 2;
    const int lq   = (tid & 3) << 2;
    const int bcl  = tid & 127;         // B loader col
    const int brg  = tid >> 7;          // 0..1
    const int tx   = tid & 15, ty = tid >> 4;
    float acc[8][8];
    #pragma unroll
    for (int i = 0; i < 8; i++)
        #pragma unroll
        for (int j = 0; j < 8; j++) acc[i][j] = 0.0f;

    float4 a0, a1;
    float bv[8];
    {
        a0 = *(const float4*)&w[(lrow) * 256 + lq];
        a1 = *(const float4*)&w[(lrow + 64) * 256 + lq];
        int lcol = l0 + bcl;
        #pragma unroll
        for (int s = 0; s < 8; s++) {
            int pr = brg * 8 + s;
            bv[s] = (lcol < LL) ? g_final[((size_t)bb * 256 + pr) * LL + lcol] : 0.0f;
        }
    }
    for (int k0 = 0; k0 < 256; k0 += 16) {
        __syncthreads();
        As[lq + 0][lrow] = a0.x; As[lq + 1][lrow] = a0.y; As[lq + 2][lrow] = a0.z; As[lq + 3][lrow] = a0.w;
        As[lq + 0][lrow + 64] = a1.x; As[lq + 1][lrow + 64] = a1.y; As[lq + 2][lrow + 64] = a1.z; As[lq + 3][lrow + 64] = a1.w;
        #pragma unroll
        for (int s = 0; s < 8; s++) Bs[brg * 8 + s][bcl] = bv[s];
        __syncthreads();
        int kn = k0 + 16;
        if (kn < 256) {
            a0 = *(const float4*)&w[(lrow) * 256 + kn + lq];
            a1 = *(const float4*)&w[(lrow + 64) * 256 + kn + lq];
            int lcol = l0 + bcl;
            #pragma unroll
            for (int s = 0; s < 8; s++) {
                int pr = kn + brg * 8 + s;
                bv[s] = (lcol < LL) ? g_final[((size_t)bb * 256 + pr) * LL + lcol] : 0.0f;
            }
        }
        #pragma unroll
        for (int kk = 0; kk < 16; kk++) {
            float a[8], bf[8];
            *(float4*)(a)      = *(const float4*)&As[kk][ty * 8];
            *(float4*)(a + 4)  = *(const float4*)&As[kk][ty * 8 + 4];
            *(float4*)(bf)     = *(const float4*)&Bs[kk][tx * 8];
            *(float4*)(bf + 4) = *(const float4*)&Bs[kk][tx * 8 + 4];
            #pragma unroll
            for (int i = 0; i < 8; i++)
                #pragma unroll
                for (int j = 0; j < 8; j++)
                    acc[i][j] = fmaf(a[i], bf[j], acc[i][j]);
        }
    }
    #pragma unroll
    for (int i = 0; i < 8; i++) {
        int oc = ty * 8 + i;
        float bs = bias[oc];
        #pragma unroll
        for (int j = 0; j < 8; j++) {
            int l = l0 + tx * 8 + j;
            if (l < LL)
                out[((size_t)bb * 128 + oc) * LL + l] = acc[i][j] + bs;
        }
    }
}

// ---------------- launcher ----------------
extern "C" void kernel_launch(void* const* d_in, const int* in_sizes, int n_in,
                              void* d_out, int out_size) {
    const float* x    = (const float*)d_in[0];
    const float* w    = (const float*)d_in[1];
    const float* bias = (const float*)d_in[2];
    const float* cent = (const float*)d_in[3];
    const float* temp = (const float*)d_in[4];
    float* out = (float*)d_out;

    k_unfold<<<NROWS, 256>>>(x);
    k_c2<<<64, 256>>>(cent);
    k_gemm1<<<dim3(813, 4), 256>>>(cent);
    k_softmax<<<12996, 256>>>(temp);
    k_gemm2<<<dim3(813, 2), 256>>>(cent, temp);
    k_gemm3<<<dim3(26, 32), 256>>>(w, bias, out);
}

// round 4
// speedup vs baseline: 1.5261x; 1.5261x over previous
#include <cuda_runtime.h>
#include <cstdint>

// ---------------- problem constants ----------------
#define NB    32
#define NC    64
#define HW    56
#define OHW   57
#define LL    3249           // 57*57
#define PP    256            // C*ks*ks
#define NROWS 103968         // NB*LL  (flat rows, 256 elems each)
#define KCL   512            // clusters
#define PLSZ  831744         // PP*LL

// ---------------- scratch (device globals; no allocs allowed) ----------------
__device__ float g_cols [26615808];   // [NB][PP][LL]  == flat [NROWS][256]
__device__ float g_final[26615808];   // masked final, same layout
__device__ float g_S    [53231616];   // [NROWS][512] scores -> softmax weights (in place)
__device__ float g_x2   [NROWS];
__device__ float g_c2   [KCL];
__device__ float g_centT[131072];     // centers transposed [256][512] (B for GEMM1)

// ---------------- fast math (avoid MUFU pipe) ----------------
__device__ __forceinline__ float fast_sqrtf(float q) {
    float r = __int_as_float(0x5f3759df - (__float_as_int(q) >> 1));
    r = r * fmaf(-0.5f * q, r * r, 1.5f);
    r = r * fmaf(-0.5f * q, r * r, 1.5f);
    r = r * fmaf(-0.5f * q, r * r, 1.5f);
    float s = q * r;
    return (q > 1e-20f) ? s : 0.0f;
}

__device__ __forceinline__ float fast_expf(float x) {
    x = fmaxf(x, -80.0f);
    float y  = x * 1.44269504088896f;
    float t  = y + 12582912.0f;
    float nf = t - 12582912.0f;
    float f  = y - nf;
    int   e  = (__float_as_int(t) & 0x7FFFFF) - 0x400000;
    float p  = 1.3333558146e-3f;
    p = fmaf(p, f, 9.6180905e-3f);
    p = fmaf(p, f, 5.5504108665e-2f);
    p = fmaf(p, f, 2.4022650696e-1f);
    p = fmaf(p, f, 6.9314718056e-1f);
    p = fmaf(p, f, 1.0f);
    return p * __int_as_float((e + 127) << 23);
}

__device__ __forceinline__ uint32_t tf32cvt(float x) {
    uint32_t r; asm("cvt.rna.tf32.f32 %0, %1;" : "=r"(r) : "f"(x)); return r;
}

__device__ __forceinline__ void mma_tf32(float* c, const uint32_t* a, uint32_t b0, uint32_t b1) {
    asm volatile("mma.sync.aligned.m16n8k8.row.col.f32.tf32.tf32.f32 "
        "{%0,%1,%2,%3}, {%4,%5,%6,%7}, {%8,%9}, {%0,%1,%2,%3};"
        : "+f"(c[0]), "+f"(c[1]), "+f"(c[2]), "+f"(c[3])
        : "r"(a[0]), "r"(a[1]), "r"(a[2]), "r"(a[3]), "r"(b0), "r"(b1));
}

// ---------------- kernel 1: unfold + fused row |x|^2 ----------------
__global__ void k_unfold(const float* __restrict__ x) {
    unsigned n = blockIdx.x;
    unsigned g = n * 256u + threadIdx.x;
    unsigned b   = g / PLSZ;
    unsigned rem = g - b * PLSZ;
    unsigned p   = rem / LL;
    unsigned l   = rem - p * LL;
    unsigned c  = p >> 2, ki = (p >> 1) & 1u, kj = p & 1u;
    unsigned oi = l / OHW, oj = l - oi * OHW;
    int r  = (int)(oi + ki) - 1;
    int cc = (int)(oj + kj) - 1;
    float v = 0.0f;
    if ((unsigned)r < HW && (unsigned)cc < HW)
        v = x[(((b * NC + c) * HW + (unsigned)r) * HW + (unsigned)cc)];
    g_cols[g] = v;

    float s = v * v;
    #pragma unroll
    for (int o = 16; o; o >>= 1) s += __shfl_xor_sync(0xffffffffu, s, o);
    __shared__ float ws[8];
    if ((threadIdx.x & 31) == 0) ws[threadIdx.x >> 5] = s;
    __syncthreads();
    if (threadIdx.x < 8) {
        float tsum = ws[threadIdx.x];
        #pragma unroll
        for (int o = 4; o; o >>= 1) tsum += __shfl_xor_sync(0xffu, tsum, o);
        if (threadIdx.x == 0) g_x2[n] = tsum;
    }
}

// ---------------- kernel 2: |c|^2 per center ----------------
__global__ void k_c2(const float* __restrict__ cent) {
    int k = blockIdx.x * 8 + (threadIdx.x >> 5);
    int lane = threadIdx.x & 31;
    float s = 0.0f;
    #pragma unroll
    for (int i = 0; i < 8; i++) {
        float v = cent[k * 256 + lane + 32 * i];
        s = fmaf(v, v, s);
    }
    #pragma unroll
    for (int o = 16; o; o >>= 1) s += __shfl_xor_sync(0xffffffffu, s, o);
    if (lane == 0) g_c2[k] = s;
}

// ---------------- kernel 2b: transpose centers -> g_centT [256][512] ----------------
__global__ void k_tr(const float* __restrict__ cent) {
    __shared__ float t[32][33];
    int k0 = blockIdx.x * 32, j0 = blockIdx.y * 32;
    int tx = threadIdx.x & 31, ty = threadIdx.x >> 5;
    #pragma unroll
    for (int i = 0; i < 4; i++)
        t[ty + 8 * i][tx] = cent[(k0 + ty + 8 * i) * 256 + j0 + tx];
    __syncthreads();
    #pragma unroll
    for (int i = 0; i < 4; i++)
        g_centT[(j0 + ty + 8 * i) * 512 + k0 + tx] = t[tx][ty + 8 * i];
}

// ---------------- unified tf32 mma.sync GEMM ----------------
// C[128 x 128-tile] = A[M x KTOT] * B[KTOT x N]   (A row-major, B row-major [k][n])
// MODE 1: A=g_cols (K=256), B=g_centT (stride 512)  -> g_S              grid(4, 813)
// MODE 2: A=g_S   (K=512), B=cent    (stride 256)  -> blend+mask->g_final grid(2, 813)
// MODE 3: A=w     (K=256), B=g_final slice (stride LL) -> out+bias       grid(26, 32)
// Block: 256 thr = 8 warps (warp_m 0..3 x warp_n 0..1); warp tile 32x64.
// SMEM per buffer: A frags 4096 f + B frags 4096 f; 2 buffers = 64 KB.
template<int KTOT, int MODE>
__global__ void k_mma(const float* __restrict__ cent,
                      const float* __restrict__ temp_p,
                      const float* __restrict__ w,
                      const float* __restrict__ bias,
                      float* __restrict__ out)
{
    constexpr int NCH = KTOT / 32;
    extern __shared__ float sm[];

    const int tid = threadIdx.x;
    const int lane = tid & 31, wid = tid >> 5;
    const int warp_m = wid & 3, warp_n = wid >> 2;

    const int n0 = blockIdx.x * 128;
    const int m0 = (MODE == 3) ? 0 : blockIdx.y * 128;
    const int bb = (MODE == 3) ? blockIdx.y : 0;

    const float* Aptr = (MODE == 1) ? g_cols : (MODE == 2) ? g_S : w;
    const float* Bptr = (MODE == 1) ? g_centT : (MODE == 2) ? cent
                                              : g_final + (size_t)bb * PLSZ;
    const int BSTR = (MODE == 1) ? 512 : (MODE == 2) ? 256 : LL;

    float acc[2][8][4];
    #pragma unroll
    for (int mt = 0; mt < 2; mt++)
        #pragma unroll
        for (int nt = 0; nt < 8; nt++)
            #pragma unroll
            for (int e = 0; e < 4; e++) acc[mt][nt][e] = 0.0f;

    float arv[4][4];   // staged A: 4 float4
    float brv[4][4];   // staged B

    // ---- global chunk load ----
    auto ldg = [&](int c) {
        #pragma unroll
        for (int i = 0; i < 4; i++) {
            int f = tid + i * 256;
            int row = f >> 3, q4 = f & 7;
            int m = m0 + row;
            if (MODE == 3 || m < NROWS) {
                const float4 v = *(const float4*)(Aptr + (size_t)m * KTOT + c * 32 + q4 * 4);
                arv[i][0] = v.x; arv[i][1] = v.y; arv[i][2] = v.z; arv[i][3] = v.w;
            } else {
                arv[i][0] = arv[i][1] = arv[i][2] = arv[i][3] = 0.0f;
            }
        }
        #pragma unroll
        for (int i = 0; i < 4; i++) {
            int f = tid + i * 256;
            int kr = f >> 5, nq = f & 31;
            int k = c * 32 + kr, n = n0 + nq * 4;
            if (MODE == 3) {
                #pragma unroll
                for (int e = 0; e < 4; e++)
                    brv[i][e] = (n + e < LL) ? Bptr[(size_t)k * LL + n + e] : 0.0f;
            } else {
                const float4 v = *(const float4*)(Bptr + (size_t)k * BSTR + n);
                brv[i][0] = v.x; brv[i][1] = v.y; brv[i][2] = v.z; brv[i][3] = v.w;
            }
        }
    };

    // ---- permuted store to smem frag layout ----
    // As[s][mtile][tfrag=g*4+kq][reg = mhalf + 2*khalf]
    // Bs[s][npair][tfrag=g*4+kq][reg = which*2 + khalf]
    auto sts = [&](int buf) {
        float* base = sm + buf * 8192;
        #pragma unroll
        for (int i = 0; i < 4; i++) {
            int f = tid + i * 256;
            int row = f >> 3, q4 = f & 7;
            int s = q4 >> 1, khalf = q4 & 1;
            int mt = row >> 4, mh = (row >> 3) & 1, g = row & 7;
            float* d = base + ((s * 8 + mt) * 32 + g * 4) * 4 + (mh + 2 * khalf);
            #pragma unroll
            for (int e = 0; e < 4; e++)
                d[e * 4] = __uint_as_float(tf32cvt(arv[i][e]));
        }
        float* bbase = sm + buf * 8192 + 4096;
        #pragma unroll
        for (int i = 0; i < 4; i++) {
            int f = tid + i * 256;
            int kr = f >> 5, nq = f & 31;
            int s = kr >> 3, kq = kr & 3, khalf = (kr >> 2) & 1;
            int npair = nq >> 2, which = (nq >> 1) & 1, gb = (nq & 1) * 4;
            float* d = bbase + ((s * 8 + npair) * 32 + gb * 4 + kq) * 4 + (which * 2 + khalf);
            #pragma unroll
            for (int e = 0; e < 4; e++)
                d[e * 16] = __uint_as_float(tf32cvt(brv[i][e]));
        }
    };

    auto compute = [&](int buf) {
        const float* base  = sm + buf * 8192;
        const float* bbase = base + 4096;
        #pragma unroll
        for (int s = 0; s < 4; s++) {
            uint32_t af[2][4], bf[4][4];
            #pragma unroll
            for (int mt = 0; mt < 2; mt++) {
                float4 v = *(const float4*)(base + ((s * 8 + warp_m * 2 + mt) * 32 + lane) * 4);
                af[mt][0] = __float_as_uint(v.x); af[mt][1] = __float_as_uint(v.y);
                af[mt][2] = __float_as_uint(v.z); af[mt][3] = __float_as_uint(v.w);
            }
            #pragma unroll
            for (int np = 0; np < 4; np++) {
                float4 v = *(const float4*)(bbase + ((s * 8 + warp_n * 4 + np) * 32 + lane) * 4);
                bf[np][0] = __float_as_uint(v.x); bf[np][1] = __float_as_uint(v.y);
                bf[np][2] = __float_as_uint(v.z); bf[np][3] = __float_as_uint(v.w);
            }
            #pragma unroll
            for (int mt = 0; mt < 2; mt++)
                #pragma unroll
                for (int np = 0; np < 4; np++) {
                    mma_tf32(acc[mt][np * 2],     af[mt], bf[np][0], bf[np][1]);
                    mma_tf32(acc[mt][np * 2 + 1], af[mt], bf[np][2], bf[np][3]);
                }
        }
    };

    ldg(0);
    sts(0);
    __syncthreads();
    for (int c = 0; c < NCH; c++) {
        if (c + 1 < NCH) ldg(c + 1);
        compute(c & 1);
        __syncthreads();
        if (c + 1 < NCH) { sts((c + 1) & 1); __syncthreads(); }
    }

    // ---- epilogue ----
    const int g = lane >> 2, kq = lane & 3;
    float temp = 0.f, wT = 0.f, wF = 0.f;
    if (MODE == 2) {
        temp = *temp_p;
        wT = temp / (temp + 1.0f);
        wF = 1.0f / (temp + 1.0f);
    }
    #pragma unroll
    for (int mt = 0; mt < 2; mt++) {
        int rbase = m0 + (warp_m * 2 + mt) * 16 + g;
        #pragma unroll
        for (int half = 0; half < 2; half++) {
            int r = rbase + half * 8;
            if (MODE != 3 && r >= NROWS) continue;
            if (MODE == 2) {
                unsigned rl = (unsigned)r % LL;
                #pragma unroll
                for (int nt = 0; nt < 8; nt++) {
                    int j = n0 + (warp_n * 8 + nt) * 8 + kq * 2;
                    #pragma unroll
                    for (int e = 0; e < 2; e++) {
                        unsigned rem = rl * 256u + (unsigned)(j + e);
                        unsigned p = rem / LL;
                        unsigned l = rem - p * LL;
                        unsigned lm = l % OHW;
                        unsigned ki = (p >> 1) & 1u, kj = p & 1u;
                        bool masked = (ki == 0u && l < OHW) || (ki == 1u && l >= 3192u) ||
                                      (kj == 0u && lm == 0u) || (kj == 1u && lm == 56u);
                        float av = acc[mt][nt][half * 2 + e];
                        g_final[(size_t)r * 256 + j + e] = masked ? 0.0f
                            : fmaf(wT, av, wF * g_cols[(size_t)r * 256 + j + e]);
                    }
                }
            } else if (MODE == 1) {
                #pragma unroll
                for (int nt = 0; nt < 8; nt++) {
                    int col = n0 + (warp_n * 8 + nt) * 8 + kq * 2;
                    float2 v = make_float2(acc[mt][nt][half * 2], acc[mt][nt][half * 2 + 1]);
                    *(float2*)&g_S[(size_t)r * 512 + col] = v;
                }
            } else {
                float bs = bias[r];
                #pragma unroll
                for (int nt = 0; nt < 8; nt++) {
                    int l = n0 + (warp_n * 8 + nt) * 8 + kq * 2;
                    #pragma unroll
                    for (int e = 0; e < 2; e++) {
                        if (l + e < LL)
                            out[((size_t)bb * 128 + r) * LL + l + e] =
                                acc[mt][nt][half * 2 + e] + bs;
                    }
                }
            }
        }
    }
}

// ---------------- kernel 4: softmax over 512 centers per row ----------------
__global__ void k_softmax(const float* __restrict__ temp_p) {
    __shared__ float c2s[KCL];
    for (int i = threadIdx.x; i < KCL; i += 256) c2s[i] = g_c2[i];
    __syncthreads();
    int n = blockIdx.x * 8 + (threadIdx.x >> 5);
    int lane = threadIdx.x & 31;
    float temp = *temp_p;
    float x2 = g_x2[n];
    float sc[16];
    float m = -1e30f;
    #pragma unroll
    for (int i = 0; i < 16; i++) {
        int k = lane + 32 * i;
        float s = g_S[(size_t)n * 512 + k];
        float q = fmaxf(fmaf(-2.0f, s, x2 + c2s[k]), 0.0f);
        sc[i] = -fast_sqrtf(q) * temp;
        m = fmaxf(m, sc[i]);
    }
    #pragma unroll
    for (int o = 16; o; o >>= 1) m = fmaxf(m, __shfl_xor_sync(0xffffffffu, m, o));
    float e[16];
    float sum = 0.0f;
    #pragma unroll
    for (int i = 0; i < 16; i++) { e[i] = fast_expf(sc[i] - m); sum += e[i]; }
    #pragma unroll
    for (int o = 16; o; o >>= 1) sum += __shfl_xor_sync(0xffffffffu, sum, o);
    float inv = 1.0f / sum;
    #pragma unroll
    for (int i = 0; i < 16; i++)
        g_S[(size_t)n * 512 + lane + 32 * i] = e[i] * inv;
}

// ---------------- launcher ----------------
extern "C" void kernel_launch(void* const* d_in, const int* in_sizes, int n_in,
                              void* d_out, int out_size) {
    const float* x    = (const float*)d_in[0];
    const float* w    = (const float*)d_in[1];
    const float* bias = (const float*)d_in[2];
    const float* cent = (const float*)d_in[3];
    const float* temp = (const float*)d_in[4];
    float* out = (float*)d_out;

    const int SM_BYTES = 65536;
    static bool attr_done = false;
    if (!attr_done) {
        cudaFuncSetAttribute(k_mma<256, 1>, cudaFuncAttributeMaxDynamicSharedMemorySize, SM_BYTES);
        cudaFuncSetAttribute(k_mma<512, 2>, cudaFuncAttributeMaxDynamicSharedMemorySize, SM_BYTES);
        cudaFuncSetAttribute(k_mma<256, 3>, cudaFuncAttributeMaxDynamicSharedMemorySize, SM_BYTES);
        attr_done = true;
    }

    k_unfold<<<NROWS, 256>>>(x);
    k_c2<<<64, 256>>>(cent);
    k_tr<<<dim3(16, 8), 256>>>(cent);
    k_mma<256, 1><<<dim3(4, 813), 256, SM_BYTES>>>(cent, temp, w, bias, out);
    k_softmax<<<12996, 256>>>(temp);
    k_mma<512, 2><<<dim3(2, 813), 256, SM_BYTES>>>(cent, temp, w, bias, out);
    k_mma<256, 3><<<dim3(26, 32), 256, SM_BYTES>>>(cent, temp, w, bias, out);
}

// round 5
// speedup vs baseline: 2.2342x; 1.4641x over previous
#include <cuda_runtime.h>
#include <cstdint>

// ---------------- problem constants ----------------
#define NB    32
#define NC    64
#define HW    56
#define OHW   57
#define LL    3249           // 57*57
#define PP    256            // C*ks*ks
#define NROWS 103968         // NB*LL  (flat rows, 256 elems each)
#define KCL   512            // clusters
#define PLSZ  831744         // PP*LL

// ---------------- scratch (device globals; no allocs allowed) ----------------
__device__ float g_cols [26615808];   // [NB][PP][LL] == flat [NROWS][256]  (tf32-rounded)
__device__ float g_final[26615808];   // masked final (tf32-rounded)
__device__ float g_S    [53231616];   // [NROWS][512] scores -> softmax weights (rounded)
__device__ float g_x2   [NROWS];
__device__ float g_c2   [KCL];
__device__ float g_centT[131072];     // centers^T [256][512], tf32-rounded (GEMM1 B)
__device__ float g_centR[131072];     // centers   [512][256], tf32-rounded (GEMM2 B)
__device__ float g_wR   [32768];      // weight [128][256], tf32-rounded   (GEMM3 A)

// ---------------- fast math (avoid MUFU pipe) ----------------
__device__ __forceinline__ float fast_sqrtf(float q) {
    float r = __int_as_float(0x5f3759df - (__float_as_int(q) >> 1));
    r = r * fmaf(-0.5f * q, r * r, 1.5f);
    r = r * fmaf(-0.5f * q, r * r, 1.5f);
    r = r * fmaf(-0.5f * q, r * r, 1.5f);
    float s = q * r;
    return (q > 1e-20f) ? s : 0.0f;
}

__device__ __forceinline__ float fast_expf(float x) {
    x = fmaxf(x, -80.0f);
    float y  = x * 1.44269504088896f;
    float t  = y + 12582912.0f;
    float nf = t - 12582912.0f;
    float f  = y - nf;
    int   e  = (__float_as_int(t) & 0x7FFFFF) - 0x400000;
    float p  = 1.3333558146e-3f;
    p = fmaf(p, f, 9.6180905e-3f);
    p = fmaf(p, f, 5.5504108665e-2f);
    p = fmaf(p, f, 2.4022650696e-1f);
    p = fmaf(p, f, 6.9314718056e-1f);
    p = fmaf(p, f, 1.0f);
    return p * __int_as_float((e + 127) << 23);
}

__device__ __forceinline__ uint32_t tf32cvt(float x) {
    uint32_t r; asm("cvt.rna.tf32.f32 %0, %1;" : "=r"(r) : "f"(x)); return r;
}
__device__ __forceinline__ float tf32r(float x) { return __uint_as_float(tf32cvt(x)); }

__device__ __forceinline__ void mma_tf32(float* c, const uint32_t* a, uint32_t b0, uint32_t b1) {
    asm volatile("mma.sync.aligned.m16n8k8.row.col.f32.tf32.tf32.f32 "
        "{%0,%1,%2,%3}, {%4,%5,%6,%7}, {%8,%9}, {%0,%1,%2,%3};"
        : "+f"(c[0]), "+f"(c[1]), "+f"(c[2]), "+f"(c[3])
        : "r"(a[0]), "r"(a[1]), "r"(a[2]), "r"(a[3]), "r"(b0), "r"(b1));
}

// ---------------- kernel 1: unfold (tf32-rounded) + fused row |x|^2 ----------------
__global__ void k_unfold(const float* __restrict__ x) {
    unsigned n = blockIdx.x;
    unsigned g = n * 256u + threadIdx.x;
    unsigned b   = g / PLSZ;
    unsigned rem = g - b * PLSZ;
    unsigned p   = rem / LL;
    unsigned l   = rem - p * LL;
    unsigned c  = p >> 2, ki = (p >> 1) & 1u, kj = p & 1u;
    unsigned oi = l / OHW, oj = l - oi * OHW;
    int r  = (int)(oi + ki) - 1;
    int cc = (int)(oj + kj) - 1;
    float v = 0.0f;
    if ((unsigned)r < HW && (unsigned)cc < HW)
        v = x[(((b * NC + c) * HW + (unsigned)r) * HW + (unsigned)cc)];
    v = tf32r(v);                       // consistent with HMMA operand precision
    g_cols[g] = v;

    float s = v * v;
    #pragma unroll
    for (int o = 16; o; o >>= 1) s += __shfl_xor_sync(0xffffffffu, s, o);
    __shared__ float ws[8];
    if ((threadIdx.x & 31) == 0) ws[threadIdx.x >> 5] = s;
    __syncthreads();
    if (threadIdx.x < 8) {
        float tsum = ws[threadIdx.x];
        #pragma unroll
        for (int o = 4; o; o >>= 1) tsum += __shfl_xor_sync(0xffu, tsum, o);
        if (threadIdx.x == 0) g_x2[n] = tsum;
    }
}

// ---------------- kernel 2: |c|^2 per center (on tf32-rounded values) ----------------
__global__ void k_c2(const float* __restrict__ cent) {
    int k = blockIdx.x * 8 + (threadIdx.x >> 5);
    int lane = threadIdx.x & 31;
    float s = 0.0f;
    #pragma unroll
    for (int i = 0; i < 8; i++) {
        float v = tf32r(cent[k * 256 + lane + 32 * i]);
        s = fmaf(v, v, s);
    }
    #pragma unroll
    for (int o = 16; o; o >>= 1) s += __shfl_xor_sync(0xffffffffu, s, o);
    if (lane == 0) g_c2[k] = s;
}

// ---------------- kernel 2b: rounded copy + transpose of centers ----------------
__global__ void k_tr(const float* __restrict__ cent) {
    __shared__ float t[32][33];
    int k0 = blockIdx.x * 32, j0 = blockIdx.y * 32;
    int tx = threadIdx.x & 31, ty = threadIdx.x >> 5;
    #pragma unroll
    for (int i = 0; i < 4; i++) {
        float v = tf32r(cent[(k0 + ty + 8 * i) * 256 + j0 + tx]);
        t[ty + 8 * i][tx] = v;
        g_centR[(k0 + ty + 8 * i) * 256 + j0 + tx] = v;
    }
    __syncthreads();
    #pragma unroll
    for (int i = 0; i < 4; i++)
        g_centT[(j0 + ty + 8 * i) * 512 + k0 + tx] = t[tx][ty + 8 * i];
}

// ---------------- kernel 2c: rounded copy of conv weight ----------------
__global__ void k_rw(const float* __restrict__ w) {
    int i = blockIdx.x * 256 + threadIdx.x;
    g_wR[i] = tf32r(w[i]);
}

// ---------------- unified tf32 mma.sync GEMM (cp.async 4-stage, conflict-free smem) ----
// C[128 x 128-tile] = A[M x KTOT] * B[KTOT x N]
// MODE 1: A=g_cols(K=256), B=g_centT(str 512) -> g_S                    grid(4, 813)
// MODE 2: A=g_S  (K=512), B=g_centR(str 256) -> blend+mask -> g_final  grid(2, 813)
// MODE 3: A=g_wR (K=256), B=g_final slice(str LL) -> out + bias        grid(26, 32)
// A smem [128m][32k], swizzle k4^=(m&7): 16KB. B smem [32k][136f pad]: 17408B.
template<int KTOT, int MODE>
__global__ __launch_bounds__(256) void k_mma(const float* __restrict__ temp_p,
                                             const float* __restrict__ bias,
                                             float* __restrict__ out)
{
    constexpr int NCH = KTOT / 32;
    constexpr int STG = 4;
    constexpr int AFL = 128 * 32;     // floats per A stage
    constexpr int BFL = 32 * 136;     // floats per B stage
    extern __shared__ float sm[];

    const int tid = threadIdx.x;
    const int lane = tid & 31, wid = tid >> 5;
    const int warp_m = wid & 3, warp_n = wid >> 2;
    const int g = lane >> 2, kq = lane & 3;

    const int n0 = blockIdx.x * 128;
    const int m0 = (MODE == 3) ? 0 : blockIdx.y * 128;
    const int bb = (MODE == 3) ? blockIdx.y : 0;

    const float* Aptr = (MODE == 1) ? g_cols : (MODE == 2) ? g_S : g_wR;
    const float* Bptr = (MODE == 1) ? g_centT : (MODE == 2) ? g_centR
                                              : g_final + (size_t)bb * PLSZ;
    const int BSTR = (MODE == 1) ? 512 : 256;   // MODE 3 handled separately

    const uint32_t sA = (uint32_t)__cvta_generic_to_shared(sm);
    const uint32_t sB = sA + STG * AFL * 4;

    const int arow = tid >> 3;   // 0..31 (+32 per i)
    const int ak4  = tid & 7;
    const int bkr  = tid >> 5;   // 0..7  (+8 per i)
    const int bn4  = tid & 31;

    float acc[2][8][4];
    #pragma unroll
    for (int mt = 0; mt < 2; mt++)
        #pragma unroll
        for (int nt = 0; nt < 8; nt++)
            #pragma unroll
            for (int e = 0; e < 4; e++) acc[mt][nt][e] = 0.0f;

    auto load_stage = [&](int c) {
        const int stg = c & (STG - 1);
        // ---- A: 16B cp.async, swizzled dst ----
        #pragma unroll
        for (int i = 0; i < 4; i++) {
            int ml = arow + i * 32;
            uint32_t dst = sA + (uint32_t)(stg * AFL + ml * 32 + ((ak4 ^ (ml & 7)) << 2)) * 4u;
            int m = m0 + ml;
            const float* src;
            int sz;
            if (MODE == 3 || m < NROWS) {
                src = Aptr + (size_t)m * KTOT + c * 32 + ak4 * 4;
                sz = 16;
            } else { src = Aptr; sz = 0; }
            asm volatile("cp.async.cg.shared.global [%0], [%1], 16, %2;"
                         :: "r"(dst), "l"(src), "r"(sz) : "memory");
        }
        // ---- B ----
        #pragma unroll
        for (int i = 0; i < 4; i++) {
            int k = bkr + i * 8;
            uint32_t dst = sB + (uint32_t)(stg * BFL + k * 136 + bn4 * 4) * 4u;
            if (MODE != 3) {
                const float* src = Bptr + (size_t)(c * 32 + k) * BSTR + n0 + bn4 * 4;
                asm volatile("cp.async.cg.shared.global [%0], [%1], 16;"
                             :: "r"(dst), "l"(src) : "memory");
            } else {
                #pragma unroll
                for (int e = 0; e < 4; e++) {
                    int n = n0 + bn4 * 4 + e;
                    const float* src = Bptr + (size_t)(c * 32 + k) * LL + n;
                    int sz = (n < LL) ? 4 : 0;
                    asm volatile("cp.async.ca.shared.global [%0], [%1], 4, %2;"
                                 :: "r"(dst + e * 4u), "l"((n < LL) ? src : Bptr), "r"(sz)
                                 : "memory");
                }
            }
        }
        asm volatile("cp.async.commit_group;" ::: "memory");
    };

    auto compute = [&](int c) {
        const float* Ab = sm + (c & (STG - 1)) * AFL;
        const float* Bb = sm + STG * AFL + (c & (STG - 1)) * BFL;
        #pragma unroll
        for (int s = 0; s < 4; s++) {
            uint32_t af[2][4];
            #pragma unroll
            for (int mt = 0; mt < 2; mt++) {
                #pragma unroll
                for (int r = 0; r < 4; r++) {
                    int ml = warp_m * 32 + mt * 16 + g + 8 * (r & 1);
                    int kk2 = 2 * s + (r >> 1);              // k4 of element
                    af[mt][r] = __float_as_uint(Ab[ml * 32 + ((kk2 ^ g) << 2) + kq]);
                }
            }
            uint32_t bfr[4][4];
            #pragma unroll
            for (int np = 0; np < 4; np++) {
                #pragma unroll
                for (int wch = 0; wch < 2; wch++) {
                    int n = warp_n * 64 + (np * 2 + wch) * 8 + g;
                    bfr[np][wch * 2 + 0] = __float_as_uint(Bb[(s * 8 + kq) * 136 + n]);
                    bfr[np][wch * 2 + 1] = __float_as_uint(Bb[(s * 8 + kq + 4) * 136 + n]);
                }
            }
            #pragma unroll
            for (int mt = 0; mt < 2; mt++)
                #pragma unroll
                for (int np = 0; np < 4; np++) {
                    mma_tf32(acc[mt][np * 2],     af[mt], bfr[np][0], bfr[np][1]);
                    mma_tf32(acc[mt][np * 2 + 1], af[mt], bfr[np][2], bfr[np][3]);
                }
        }
    };

    load_stage(0); load_stage(1); load_stage(2);
    for (int c = 0; c < NCH; c++) {
        if (c + 3 < NCH) {
            load_stage(c + 3);
            asm volatile("cp.async.wait_group 3;" ::: "memory");
        } else {
            asm volatile("cp.async.wait_group 0;" ::: "memory");
        }
        __syncthreads();
        compute(c);
        __syncthreads();
    }

    // ---- epilogue ----
    float temp = 0.f, wT = 0.f, wF = 0.f;
    if (MODE == 2) {
        temp = *temp_p;
        wT = temp / (temp + 1.0f);
        wF = 1.0f / (temp + 1.0f);
    }
    #pragma unroll
    for (int mt = 0; mt < 2; mt++) {
        int rbase = m0 + (warp_m * 2 + mt) * 16 + g;
        #pragma unroll
        for (int half = 0; half < 2; half++) {
            int r = rbase + half * 8;
            if (MODE != 3 && r >= NROWS) continue;
            if (MODE == 2) {
                unsigned rl = (unsigned)r % LL;
                #pragma unroll
                for (int nt = 0; nt < 8; nt++) {
                    int j = n0 + (warp_n * 8 + nt) * 8 + kq * 2;
                    #pragma unroll
                    for (int e = 0; e < 2; e++) {
                        unsigned rem = rl * 256u + (unsigned)(j + e);
                        unsigned p = rem / LL;
                        unsigned l = rem - p * LL;
                        unsigned lm = l % OHW;
                        unsigned ki = (p >> 1) & 1u, kj = p & 1u;
                        bool masked = (ki == 0u && l < OHW) || (ki == 1u && l >= 3192u) ||
                                      (kj == 0u && lm == 0u) || (kj == 1u && lm == 56u);
                        float av = acc[mt][nt][half * 2 + e];
                        float val = masked ? 0.0f
                            : fmaf(wT, av, wF * g_cols[(size_t)r * 256 + j + e]);
                        g_final[(size_t)r * 256 + j + e] = tf32r(val);
                    }
                }
            } else if (MODE == 1) {
                #pragma unroll
                for (int nt = 0; nt < 8; nt++) {
                    int col = n0 + (warp_n * 8 + nt) * 8 + kq * 2;
                    float2 v = make_float2(acc[mt][nt][half * 2], acc[mt][nt][half * 2 + 1]);
                    *(float2*)&g_S[(size_t)r * 512 + col] = v;
                }
            } else {
                float bs = bias[r];
                #pragma unroll
                for (int nt = 0; nt < 8; nt++) {
                    int l = n0 + (warp_n * 8 + nt) * 8 + kq * 2;
                    #pragma unroll
                    for (int e = 0; e < 2; e++) {
                        if (l + e < LL)
                            out[((size_t)bb * 128 + r) * LL + l + e] =
                                acc[mt][nt][half * 2 + e] + bs;
                    }
                }
            }
        }
    }
}

// ---------------- kernel 4: softmax over 512 centers per row (rounded output) -------
__global__ void k_softmax(const float* __restrict__ temp_p) {
    __shared__ float c2s[KCL];
    for (int i = threadIdx.x; i < KCL; i += 256) c2s[i] = g_c2[i];
    __syncthreads();
    int n = blockIdx.x * 8 + (threadIdx.x >> 5);
    int lane = threadIdx.x & 31;
    float temp = *temp_p;
    float x2 = g_x2[n];
    float sc[16];
    float m = -1e30f;
    #pragma unroll
    for (int i = 0; i < 16; i++) {
        int k = lane + 32 * i;
        float s = g_S[(size_t)n * 512 + k];
        float q = fmaxf(fmaf(-2.0f, s, x2 + c2s[k]), 0.0f);
        sc[i] = -fast_sqrtf(q) * temp;
        m = fmaxf(m, sc[i]);
    }
    #pragma unroll
    for (int o = 16; o; o >>= 1) m = fmaxf(m, __shfl_xor_sync(0xffffffffu, m, o));
    float e[16];
    float sum = 0.0f;
    #pragma unroll
    for (int i = 0; i < 16; i++) { e[i] = fast_expf(sc[i] - m); sum += e[i]; }
    #pragma unroll
    for (int o = 16; o; o >>= 1) sum += __shfl_xor_sync(0xffffffffu, sum, o);
    float inv = 1.0f / sum;
    #pragma unroll
    for (int i = 0; i < 16; i++)
        g_S[(size_t)n * 512 + lane + 32 * i] = tf32r(e[i] * inv);
}

// ---------------- launcher ----------------
extern "C" void kernel_launch(void* const* d_in, const int* in_sizes, int n_in,
                              void* d_out, int out_size) {
    const float* x    = (const float*)d_in[0];
    const float* w    = (const float*)d_in[1];
    const float* bias = (const float*)d_in[2];
    const float* cent = (const float*)d_in[3];
    const float* temp = (const float*)d_in[4];
    float* out = (float*)d_out;

    const int SM_BYTES = 4 * (128 * 32 + 32 * 136) * 4;   // 135168
    static bool attr_done = false;
    if (!attr_done) {
        cudaFuncSetAttribute(k_mma<256, 1>, cudaFuncAttributeMaxDynamicSharedMemorySize, SM_BYTES);
        cudaFuncSetAttribute(k_mma<512, 2>, cudaFuncAttributeMaxDynamicSharedMemorySize, SM_BYTES);
        cudaFuncSetAttribute(k_mma<256, 3>, cudaFuncAttributeMaxDynamicSharedMemorySize, SM_BYTES);
        attr_done = true;
    }

    k_unfold<<<NROWS, 256>>>(x);
    k_c2<<<64, 256>>>(cent);
    k_tr<<<dim3(16, 8), 256>>>(cent);
    k_rw<<<128, 256>>>(w);
    k_mma<256, 1><<<dim3(4, 813), 256, SM_BYTES>>>(temp, bias, out);
    k_softmax<<<12996, 256>>>(temp);
    k_mma<512, 2><<<dim3(2, 813), 256, SM_BYTES>>>(temp, bias, out);
    k_mma<256, 3><<<dim3(26, 32), 256, SM_BYTES>>>(temp, bias, out);
}

// round 9
// speedup vs baseline: 2.3559x; 1.0545x over previous
#include <cuda_runtime.h>
#include <cstdint>

// ---------------- problem constants ----------------
#define NB    32
#define NC    64
#define HW    56
#define OHW   57
#define LL    3249           // 57*57
#define LLP   3252           // LL padded to multiple of 4 (16B-aligned rows)
#define PP    256            // C*ks*ks
#define NROWS 103968         // NB*LL
#define KCL   512
#define PLSZ  831744         // PP*LL
#define PLSZP 832512         // PP*LLP

// ---------------- scratch ----------------
__device__ float g_cols  [26615808];  // flat [NROWS][256] == [NB][PP][LL], tf32-rounded
__device__ float g_finalP[26640400];  // masked final, PADDED [NB][PP][LLP] (+16 tail pad)
__device__ float g_S     [53231616];  // [NROWS][512] scores -> softmax weights
__device__ float g_x2    [NROWS];
__device__ float g_c2    [KCL];
__device__ float g_centT [131072];    // centers^T [256][512] rounded (GEMM1 B, [k][n])
__device__ float g_centR [131072];    // centers   [512][256] rounded (GEMM2 B, [k][n])
__device__ float g_wR    [32768];     // weight [128][256] rounded    (GEMM3 A)

// ---------------- fast math ----------------
__device__ __forceinline__ float fast_sqrtf(float q) {
    float r = __int_as_float(0x5f3759df - (__float_as_int(q) >> 1));
    r = r * fmaf(-0.5f * q, r * r, 1.5f);
    r = r * fmaf(-0.5f * q, r * r, 1.5f);
    r = r * fmaf(-0.5f * q, r * r, 1.5f);
    float s = q * r;
    return (q > 1e-20f) ? s : 0.0f;
}
__device__ __forceinline__ float fast_expf(float x) {
    x = fmaxf(x, -80.0f);
    float y  = x * 1.44269504088896f;
    float t  = y + 12582912.0f;
    float f  = y - (t - 12582912.0f);
    int   e  = (__float_as_int(t) & 0x7FFFFF) - 0x400000;
    float p  = 1.3333558146e-3f;
    p = fmaf(p, f, 9.6180905e-3f);
    p = fmaf(p, f, 5.5504108665e-2f);
    p = fmaf(p, f, 2.4022650696e-1f);
    p = fmaf(p, f, 6.9314718056e-1f);
    p = fmaf(p, f, 1.0f);
    return p * __int_as_float((e + 127) << 23);
}
__device__ __forceinline__ uint32_t tf32cvt(float x) {
    uint32_t r; asm("cvt.rna.tf32.f32 %0, %1;" : "=r"(r) : "f"(x)); return r;
}
__device__ __forceinline__ float tf32r(float x) { return __uint_as_float(tf32cvt(x)); }

__device__ __forceinline__ void mma_tf32(float* c, const uint32_t* a, uint32_t b0, uint32_t b1) {
    asm volatile("mma.sync.aligned.m16n8k8.row.col.f32.tf32.tf32.f32 "
        "{%0,%1,%2,%3}, {%4,%5,%6,%7}, {%8,%9}, {%0,%1,%2,%3};"
        : "+f"(c[0]), "+f"(c[1]), "+f"(c[2]), "+f"(c[3])
        : "r"(a[0]), "r"(a[1]), "r"(a[2]), "r"(a[3]), "r"(b0), "r"(b1));
}

// ---------------- kernel 1: unfold (warp per flat row) ----------------
__global__ void k_unfold(const float* __restrict__ x) {
    int row = blockIdx.x * 8 + (threadIdx.x >> 5);
    int lane = threadIdx.x & 31;
    float s = 0.f;
    #pragma unroll
    for (int i = 0; i < 8; i++) {
        unsigned g = (unsigned)row * 256u + lane + 32u * i;
        unsigned b   = g / PLSZ;
        unsigned rem = g - b * PLSZ;
        unsigned p   = rem / LL;
        unsigned l   = rem - p * LL;
        unsigned c  = p >> 2, ki = (p >> 1) & 1u, kj = p & 1u;
        unsigned oi = l / OHW, oj = l - oi * OHW;
        int r  = (int)(oi + ki) - 1;
        int cc = (int)(oj + kj) - 1;
        float v = 0.0f;
        if ((unsigned)r < HW && (unsigned)cc < HW)
            v = x[(((b * NC + c) * HW + (unsigned)r) * HW + (unsigned)cc)];
        v = tf32r(v);
        g_cols[g] = v;
        s = fmaf(v, v, s);
    }
    #pragma unroll
    for (int o = 16; o; o >>= 1) s += __shfl_xor_sync(0xffffffffu, s, o);
    if (lane == 0) g_x2[row] = s;
}

// ---------------- kernel 2: |c|^2 ----------------
__global__ void k_c2(const float* __restrict__ cent) {
    int k = blockIdx.x * 8 + (threadIdx.x >> 5);
    int lane = threadIdx.x & 31;
    float s = 0.0f;
    #pragma unroll
    for (int i = 0; i < 8; i++) {
        float v = tf32r(cent[k * 256 + lane + 32 * i]);
        s = fmaf(v, v, s);
    }
    #pragma unroll
    for (int o = 16; o; o >>= 1) s += __shfl_xor_sync(0xffffffffu, s, o);
    if (lane == 0) g_c2[k] = s;
}

// ---------------- kernel 2b: rounded copy + transpose of centers ----------------
__global__ void k_tr(const float* __restrict__ cent) {
    __shared__ float t[32][33];
    int k0 = blockIdx.x * 32, j0 = blockIdx.y * 32;
    int tx = threadIdx.x & 31, ty = threadIdx.x >> 5;
    #pragma unroll
    for (int i = 0; i < 4; i++) {
        float v = tf32r(cent[(k0 + ty + 8 * i) * 256 + j0 + tx]);
        t[ty + 8 * i][tx] = v;
        g_centR[(k0 + ty + 8 * i) * 256 + j0 + tx] = v;
    }
    __syncthreads();
    #pragma unroll
    for (int i = 0; i < 4; i++)
        g_centT[(j0 + ty + 8 * i) * 512 + k0 + tx] = t[tx][ty + 8 * i];
}

// ---------------- kernel 2c: rounded copy of conv weight ----------------
__global__ void k_rw(const float* __restrict__ w) {
    int i = blockIdx.x * 256 + threadIdx.x;
    g_wR[i] = tf32r(w[i]);
}

// ---------------- unified tf32 mma.sync GEMM (cp.async 4-stage) ----------------
// C[128 x 128-tile] = A[M x KTOT] * B[KTOT x N]
// MODE 1: A=g_cols(K=256), B=g_centT [256][512]   -> g_S                  grid(4, 813)
// MODE 2: A=g_S  (K=512), B=g_centR [512][256]   -> blend+mask->g_finalP grid(2, 813)
// MODE 3: A=g_wR (K=256), B=g_finalP[b] [256][LLP] -> out + bias          grid(26, 32)
//   (LLP=3252 is a multiple of 4 => every MODE3 16B cp.async src is aligned)
// A smem [128m][32k], swizzle k4^=(m&7): 16KB/stage.
// B smem [32k][132f pad] (B-frag LDS 2-way max): 16896B/stage.
template<int KTOT, int MODE>
__global__ __launch_bounds__(256) void k_mma(const float* __restrict__ temp_p,
                                             const float* __restrict__ bias,
                                             float* __restrict__ out)
{
    constexpr int NCH = KTOT / 32;
    constexpr int STG = 4;
    constexpr int AFL = 128 * 32;     // floats per A stage
    constexpr int BFL = 32 * 132;     // floats per B stage
    extern __shared__ float sm[];

    const int tid = threadIdx.x;
    const int lane = tid & 31, wid = tid >> 5;
    const int warp_m = wid & 3, warp_n = wid >> 2;
    const int g = lane >> 2, kq = lane & 3;

    const int n0 = blockIdx.x * 128;
    const int m0 = (MODE == 3) ? 0 : blockIdx.y * 128;
    const int bb = (MODE == 3) ? blockIdx.y : 0;

    const float* Aptr = (MODE == 1) ? g_cols : (MODE == 2) ? g_S : g_wR;
    const float* Bptr = (MODE == 1) ? g_centT : (MODE == 2) ? g_centR
                                              : g_finalP + (size_t)bb * PLSZP;
    const int BSTR = (MODE == 1) ? 512 : (MODE == 2) ? 256 : LLP;

    const uint32_t sA = (uint32_t)__cvta_generic_to_shared(sm);
    const uint32_t sB = sA + STG * AFL * 4;

    const int arow = tid >> 3;   // 0..31 (+32 per i)
    const int ak4  = tid & 7;
    const int bkr  = tid >> 5;   // 0..7  (+8 per i)
    const int bn4  = tid & 31;

    float acc[2][8][4];
    #pragma unroll
    for (int mt = 0; mt < 2; mt++)
        #pragma unroll
        for (int nt = 0; nt < 8; nt++)
            #pragma unroll
            for (int e = 0; e < 4; e++) acc[mt][nt][e] = 0.0f;

    auto load_stage = [&](int c) {
        const int stg = c & (STG - 1);
        // ---- A: 16B cp.async, swizzled dst ----
        #pragma unroll
        for (int i = 0; i < 4; i++) {
            int ml = arow + i * 32;
            uint32_t dst = sA + (uint32_t)(stg * AFL + ml * 32 + ((ak4 ^ (ml & 7)) << 2)) * 4u;
            int m = m0 + ml;
            bool ok = (MODE == 3) || (m < NROWS);
            const float* src = ok ? (Aptr + (size_t)m * KTOT + c * 32 + ak4 * 4) : Aptr;
            int sz = ok ? 16 : 0;
            asm volatile("cp.async.cg.shared.global [%0], [%1], 16, %2;"
                         :: "r"(dst), "l"(src), "r"(sz) : "memory");
        }
        // ---- B: [k][n4] 16B cp.async (all sources 16B-aligned; MODE3 via LLP) ----
        #pragma unroll
        for (int i = 0; i < 4; i++) {
            int k = bkr + i * 8;
            uint32_t dst = sB + (uint32_t)(stg * BFL + k * 132 + bn4 * 4) * 4u;
            int n = n0 + bn4 * 4;
            bool ok = (MODE != 3) || (n < LL);   // n<LL => read ends at n+3<=3251<LLP, in-row
            const float* src = ok ? (Bptr + (size_t)(c * 32 + k) * BSTR + n) : Bptr;
            int sz = ok ? 16 : 0;
            asm volatile("cp.async.cg.shared.global [%0], [%1], 16, %2;"
                         :: "r"(dst), "l"(src), "r"(sz) : "memory");
        }
        asm volatile("cp.async.commit_group;" ::: "memory");
    };

    auto compute = [&](int c) {
        const float* Ab = sm + (c & (STG - 1)) * AFL;
        const float* Bb = sm + STG * AFL + (c & (STG - 1)) * BFL;
        #pragma unroll
        for (int s = 0; s < 4; s++) {
            uint32_t af[2][4];
            #pragma unroll
            for (int mt = 0; mt < 2; mt++) {
                #pragma unroll
                for (int r = 0; r < 4; r++) {
                    int ml = warp_m * 32 + mt * 16 + g + 8 * (r & 1);
                    int kk2 = 2 * s + (r >> 1);
                    af[mt][r] = __float_as_uint(Ab[ml * 32 + ((kk2 ^ g) << 2) + kq]);
                }
            }
            uint32_t bfr[4][4];
            #pragma unroll
            for (int np = 0; np < 4; np++) {
                #pragma unroll
                for (int wch = 0; wch < 2; wch++) {
                    int n = warp_n * 64 + (np * 2 + wch) * 8 + g;
                    bfr[np][wch * 2 + 0] = __float_as_uint(Bb[(s * 8 + kq) * 132 + n]);
                    bfr[np][wch * 2 + 1] = __float_as_uint(Bb[(s * 8 + kq + 4) * 132 + n]);
                }
            }
            #pragma unroll
            for (int mt = 0; mt < 2; mt++)
                #pragma unroll
                for (int np = 0; np < 4; np++) {
                    mma_tf32(acc[mt][np * 2],     af[mt], bfr[np][0], bfr[np][1]);
                    mma_tf32(acc[mt][np * 2 + 1], af[mt], bfr[np][2], bfr[np][3]);
                }
        }
    };

    load_stage(0); load_stage(1); load_stage(2);
    for (int c = 0; c < NCH; c++) {
        if (c + 3 < NCH) {
            load_stage(c + 3);
            asm volatile("cp.async.wait_group 3;" ::: "memory");
        } else {
            asm volatile("cp.async.wait_group 0;" ::: "memory");
        }
        __syncthreads();
        compute(c);
        __syncthreads();
    }

    // ---- epilogue ----
    float temp = 0.f, wT = 0.f, wF = 0.f;
    if (MODE == 2) {
        temp = *temp_p;
        wT = temp / (temp + 1.0f);
        wF = 1.0f / (temp + 1.0f);
    }
    #pragma unroll
    for (int mt = 0; mt < 2; mt++) {
        int rbase = m0 + (warp_m * 2 + mt) * 16 + g;
        #pragma unroll
        for (int half = 0; half < 2; half++) {
            int r = rbase + half * 8;
            if (MODE != 3 && r >= NROWS) continue;
            if (MODE == 2) {
                unsigned rl = (unsigned)r % LL;
                unsigned b  = (unsigned)r / LL;
                size_t dstb = (size_t)b * PLSZP;
                #pragma unroll
                for (int nt = 0; nt < 8; nt++) {
                    int j = n0 + (warp_n * 8 + nt) * 8 + kq * 2;
                    #pragma unroll
                    for (int e = 0; e < 2; e++) {
                        unsigned rem = rl * 256u + (unsigned)(j + e);
                        unsigned p = rem / LL;
                        unsigned l = rem - p * LL;
                        unsigned lm = l % OHW;
                        unsigned ki = (p >> 1) & 1u, kj = p & 1u;
                        bool masked = (ki == 0u && l < OHW) || (ki == 1u && l >= 3192u) ||
                                      (kj == 0u && lm == 0u) || (kj == 1u && lm == 56u);
                        float av = acc[mt][nt][half * 2 + e];
                        float val = masked ? 0.0f
                            : fmaf(wT, av, wF * g_cols[(size_t)r * 256 + j + e]);
                        g_finalP[dstb + (size_t)p * LLP + l] = tf32r(val);
                    }
                }
            } else if (MODE == 1) {
                #pragma unroll
                for (int nt = 0; nt < 8; nt++) {
                    int col = n0 + (warp_n * 8 + nt) * 8 + kq * 2;
                    float2 v = make_float2(acc[mt][nt][half * 2], acc[mt][nt][half * 2 + 1]);
                    *(float2*)&g_S[(size_t)r * 512 + col] = v;
                }
            } else {
                float bs = bias[r];
                #pragma unroll
                for (int nt = 0; nt < 8; nt++) {
                    int l = n0 + (warp_n * 8 + nt) * 8 + kq * 2;
                    #pragma unroll
                    for (int e = 0; e < 2; e++) {
                        if (l + e < LL)
                            out[((size_t)bb * 128 + r) * LL + l + e] =
                                acc[mt][nt][half * 2 + e] + bs;
                    }
                }
            }
        }
    }
}

// ---------------- kernel 4: softmax over 512 centers per row (rounded output) -------
__global__ void k_softmax(const float* __restrict__ temp_p) {
    __shared__ float c2s[KCL];
    for (int i = threadIdx.x; i < KCL; i += 256) c2s[i] = g_c2[i];
    __syncthreads();
    int n = blockIdx.x * 8 + (threadIdx.x >> 5);
    int lane = threadIdx.x & 31;
    float temp = *temp_p;
    float x2 = g_x2[n];
    float sc[16];
    float m = -1e30f;
    #pragma unroll
    for (int i = 0; i < 16; i++) {
        int k = lane + 32 * i;
        float s = g_S[(size_t)n * 512 + k];
        float q = fmaxf(fmaf(-2.0f, s, x2 + c2s[k]), 0.0f);
        sc[i] = -fast_sqrtf(q) * temp;
        m = fmaxf(m, sc[i]);
    }
    #pragma unroll
    for (int o = 16; o; o >>= 1) m = fmaxf(m, __shfl_xor_sync(0xffffffffu, m, o));
    float e[16];
    float sum = 0.0f;
    #pragma unroll
    for (int i = 0; i < 16; i++) { e[i] = fast_expf(sc[i] - m); sum += e[i]; }
    #pragma unroll
    for (int o = 16; o; o >>= 1) sum += __shfl_xor_sync(0xffffffffu, sum, o);
    float inv = 1.0f / sum;
    #pragma unroll
    for (int i = 0; i < 16; i++)
        g_S[(size_t)n * 512 + lane + 32 * i] = tf32r(e[i] * inv);
}

// ---------------- launcher ----------------
extern "C" void kernel_launch(void* const* d_in, const int* in_sizes, int n_in,
                              void* d_out, int out_size) {
    const float* x    = (const float*)d_in[0];
    const float* w    = (const float*)d_in[1];
    const float* bias = (const float*)d_in[2];
    const float* cent = (const float*)d_in[3];
    const float* temp = (const float*)d_in[4];
    float* out = (float*)d_out;

    const int SM_BYTES = 4 * (128 * 32 + 32 * 132) * 4;   // 133120
    cudaFuncSetAttribute(k_mma<256, 1>, cudaFuncAttributeMaxDynamicSharedMemorySize, SM_BYTES);
    cudaFuncSetAttribute(k_mma<512, 2>, cudaFuncAttributeMaxDynamicSharedMemorySize, SM_BYTES);
    cudaFuncSetAttribute(k_mma<256, 3>, cudaFuncAttributeMaxDynamicSharedMemorySize, SM_BYTES);

    k_unfold<<<12996, 256>>>(x);
    k_c2<<<64, 256>>>(cent);
    k_tr<<<dim3(16, 8), 256>>>(cent);
    k_rw<<<128, 256>>>(w);
    k_mma<256, 1><<<dim3(4, 813), 256, SM_BYTES>>>(temp, bias, out);
    k_softmax<<<12996, 256>>>(temp);
    k_mma<512, 2><<<dim3(2, 813), 256, SM_BYTES>>>(temp, bias, out);
    k_mma<256, 3><<<dim3(26, 32), 256, SM_BYTES>>>(temp, bias, out);
}

// round 10
// speedup vs baseline: 2.5821x; 1.0960x over previous
#include <cuda_runtime.h>
#include <cstdint>

// ---------------- problem constants ----------------
#define NB    32
#define NC    64
#define HW    56
#define OHW   57
#define LL    3249           // 57*57
#define LLP   3252           // LL padded to multiple of 4 (16B-aligned rows)
#define PP    256            // C*ks*ks
#define NROWS 103968         // NB*LL
#define KCL   512
#define PLSZ  831744         // PP*LL
#define PLSZP 832512         // PP*LLP

// ---------------- scratch ----------------
__device__ float g_cols  [26615808];  // flat [NROWS][256] == [NB][PP][LL], tf32-rounded
__device__ float g_finalP[26640400];  // masked final, PADDED [NB][PP][LLP] (+16 tail pad)
__device__ float g_S     [53231616];  // [NROWS][512] scores -> softmax weights
__device__ float g_x2    [NROWS];
__device__ float g_c2    [KCL];
__device__ float g_centT [131072];    // centers^T [256][512] rounded (GEMM1 B, [k][n])
__device__ float g_centR [131072];    // centers   [512][256] rounded (GEMM2 B, [k][n])
__device__ float g_wR    [32768];     // weight [128][256] rounded    (GEMM3 A)

// ---------------- fast math ----------------
__device__ __forceinline__ float fast_sqrtf(float q) {
    float r = __int_as_float(0x5f3759df - (__float_as_int(q) >> 1));
    r = r * fmaf(-0.5f * q, r * r, 1.5f);
    r = r * fmaf(-0.5f * q, r * r, 1.5f);
    r = r * fmaf(-0.5f * q, r * r, 1.5f);
    float s = q * r;
    return (q > 1e-20f) ? s : 0.0f;
}
__device__ __forceinline__ float fast_expf(float x) {
    x = fmaxf(x, -80.0f);
    float y  = x * 1.44269504088896f;
    float t  = y + 12582912.0f;
    float f  = y - (t - 12582912.0f);
    int   e  = (__float_as_int(t) & 0x7FFFFF) - 0x400000;
    float p  = 1.3333558146e-3f;
    p = fmaf(p, f, 9.6180905e-3f);
    p = fmaf(p, f, 5.5504108665e-2f);
    p = fmaf(p, f, 2.4022650696e-1f);
    p = fmaf(p, f, 6.9314718056e-1f);
    p = fmaf(p, f, 1.0f);
    return p * __int_as_float((e + 127) << 23);
}
__device__ __forceinline__ uint32_t tf32cvt(float x) {
    uint32_t r; asm("cvt.rna.tf32.f32 %0, %1;" : "=r"(r) : "f"(x)); return r;
}
__device__ __forceinline__ float tf32r(float x) { return __uint_as_float(tf32cvt(x)); }

__device__ __forceinline__ void mma_tf32(float* c, const uint32_t* a, uint32_t b0, uint32_t b1) {
    asm volatile("mma.sync.aligned.m16n8k8.row.col.f32.tf32.tf32.f32 "
        "{%0,%1,%2,%3}, {%4,%5,%6,%7}, {%8,%9}, {%0,%1,%2,%3};"
        : "+f"(c[0]), "+f"(c[1]), "+f"(c[2]), "+f"(c[3])
        : "r"(a[0]), "r"(a[1]), "r"(a[2]), "r"(a[3]), "r"(b0), "r"(b1));
}

// ---------------- kernel 1: unfold (warp per flat row) ----------------
__global__ void k_unfold(const float* __restrict__ x) {
    int row = blockIdx.x * 8 + (threadIdx.x >> 5);
    int lane = threadIdx.x & 31;
    float s = 0.f;
    #pragma unroll
    for (int i = 0; i < 8; i++) {
        unsigned g = (unsigned)row * 256u + lane + 32u * i;
        unsigned b   = g / PLSZ;
        unsigned rem = g - b * PLSZ;
        unsigned p   = rem / LL;
        unsigned l   = rem - p * LL;
        unsigned c  = p >> 2, ki = (p >> 1) & 1u, kj = p & 1u;
        unsigned oi = l / OHW, oj = l - oi * OHW;
        int r  = (int)(oi + ki) - 1;
        int cc = (int)(oj + kj) - 1;
        float v = 0.0f;
        if ((unsigned)r < HW && (unsigned)cc < HW)
            v = x[(((b * NC + c) * HW + (unsigned)r) * HW + (unsigned)cc)];
        v = tf32r(v);
        g_cols[g] = v;
        s = fmaf(v, v, s);
    }
    #pragma unroll
    for (int o = 16; o; o >>= 1) s += __shfl_xor_sync(0xffffffffu, s, o);
    if (lane == 0) g_x2[row] = s;
}

// ---------------- kernel 2: |c|^2 ----------------
__global__ void k_c2(const float* __restrict__ cent) {
    int k = blockIdx.x * 8 + (threadIdx.x >> 5);
    int lane = threadIdx.x & 31;
    float s = 0.0f;
    #pragma unroll
    for (int i = 0; i < 8; i++) {
        float v = tf32r(cent[k * 256 + lane + 32 * i]);
        s = fmaf(v, v, s);
    }
    #pragma unroll
    for (int o = 16; o; o >>= 1) s += __shfl_xor_sync(0xffffffffu, s, o);
    if (lane == 0) g_c2[k] = s;
}

// ---------------- kernel 2b: rounded copy + transpose of centers ----------------
__global__ void k_tr(const float* __restrict__ cent) {
    __shared__ float t[32][33];
    int k0 = blockIdx.x * 32, j0 = blockIdx.y * 32;
    int tx = threadIdx.x & 31, ty = threadIdx.x >> 5;
    #pragma unroll
    for (int i = 0; i < 4; i++) {
        float v = tf32r(cent[(k0 + ty + 8 * i) * 256 + j0 + tx]);
        t[ty + 8 * i][tx] = v;
        g_centR[(k0 + ty + 8 * i) * 256 + j0 + tx] = v;
    }
    __syncthreads();
    #pragma unroll
    for (int i = 0; i < 4; i++)
        g_centT[(j0 + ty + 8 * i) * 512 + k0 + tx] = t[tx][ty + 8 * i];
}

// ---------------- kernel 2c: rounded copy of conv weight ----------------
__global__ void k_rw(const float* __restrict__ w) {
    int i = blockIdx.x * 256 + threadIdx.x;
    g_wR[i] = tf32r(w[i]);
}

// ---------------- unified tf32 mma.sync GEMM (512 thr, 128x256 tile, 3-stage) ------
// C[128 x 256-tile] = A[M x KTOT] * B[KTOT x N]
// MODE 1: A=g_cols(K=256), B=g_centT [256][512]    -> g_S                 grid(2, 813)
// MODE 2: A=g_S  (K=512), B=g_centR [512][256]    -> blend+mask->g_finalP grid(1, 813)
// MODE 3: A=g_wR (K=256), B=g_finalP[b] [256][LLP] -> out + bias           grid(13, 32)
// 16 warps: warp_m 0..3 (x32 rows), warp_n 0..3 (x64 cols); warp tile 32x64.
// A smem [128m][32k] swizzle k4^=(m&7); B smem [32k][260f pad] (2-way LDS max).
template<int KTOT, int MODE>
__global__ __launch_bounds__(512) void k_mma(const float* __restrict__ temp_p,
                                             const float* __restrict__ bias,
                                             float* __restrict__ out)
{
    constexpr int NCH = KTOT / 32;
    constexpr int STG = 3;
    constexpr int AFL = 128 * 32;     // floats per A stage
    constexpr int BFL = 32 * 260;     // floats per B stage
    extern __shared__ float sm[];

    const int tid = threadIdx.x;
    const int lane = tid & 31, wid = tid >> 5;
    const int warp_m = wid & 3, warp_n = wid >> 2;     // 4 x 4 warps
    const int g = lane >> 2, kq = lane & 3;

    const int n0 = blockIdx.x * 256;
    const int m0 = (MODE == 3) ? 0 : blockIdx.y * 128;
    const int bb = (MODE == 3) ? blockIdx.y : 0;

    const float* Aptr = (MODE == 1) ? g_cols : (MODE == 2) ? g_S : g_wR;
    const float* Bptr = (MODE == 1) ? g_centT : (MODE == 2) ? g_centR
                                              : g_finalP + (size_t)bb * PLSZP;
    const int BSTR = (MODE == 1) ? 512 : (MODE == 2) ? 256 : LLP;

    const uint32_t sA = (uint32_t)__cvta_generic_to_shared(sm);
    const uint32_t sB = sA + STG * AFL * 4;

    float acc[2][8][4];
    #pragma unroll
    for (int mt = 0; mt < 2; mt++)
        #pragma unroll
        for (int nt = 0; nt < 8; nt++)
            #pragma unroll
            for (int e = 0; e < 4; e++) acc[mt][nt][e] = 0.0f;

    auto load_stage = [&](int c) {
        const int stg = c % STG;
        // ---- A: 1024 16B units, 2 per thread ----
        #pragma unroll
        for (int i = 0; i < 2; i++) {
            int ml = (tid >> 3) + i * 64;
            int k4 = tid & 7;
            uint32_t dst = sA + (uint32_t)(stg * AFL + ml * 32 + ((k4 ^ (ml & 7)) << 2)) * 4u;
            int m = m0 + ml;
            bool ok = (MODE == 3) || (m < NROWS);
            const float* src = ok ? (Aptr + (size_t)m * KTOT + c * 32 + k4 * 4) : Aptr;
            int sz = ok ? 16 : 0;
            asm volatile("cp.async.cg.shared.global [%0], [%1], 16, %2;"
                         :: "r"(dst), "l"(src), "r"(sz) : "memory");
        }
        // ---- B: [k][n4] 2048 16B units, 4 per thread ----
        #pragma unroll
        for (int i = 0; i < 4; i++) {
            int f = tid + i * 512;
            int k = f >> 6, n4 = f & 63;
            uint32_t dst = sB + (uint32_t)(stg * BFL + k * 260 + n4 * 4) * 4u;
            int n = n0 + n4 * 4;
            bool ok = (MODE != 3) || (n < LL);   // MODE3: read may touch row pad (< LLP), cols discarded
            const float* src = ok ? (Bptr + (size_t)(c * 32 + k) * BSTR + n) : Bptr;
            int sz = ok ? 16 : 0;
            asm volatile("cp.async.cg.shared.global [%0], [%1], 16, %2;"
                         :: "r"(dst), "l"(src), "r"(sz) : "memory");
        }
        asm volatile("cp.async.commit_group;" ::: "memory");
    };

    auto compute = [&](int c) {
        const float* Ab = sm + (c % STG) * AFL;
        const float* Bb = sm + STG * AFL + (c % STG) * BFL;
        #pragma unroll
        for (int s = 0; s < 4; s++) {
            uint32_t af[2][4];
            #pragma unroll
            for (int mt = 0; mt < 2; mt++) {
                #pragma unroll
                for (int r = 0; r < 4; r++) {
                    int ml = warp_m * 32 + mt * 16 + g + 8 * (r & 1);
                    int kk2 = 2 * s + (r >> 1);
                    af[mt][r] = __float_as_uint(Ab[ml * 32 + ((kk2 ^ g) << 2) + kq]);
                }
            }
            uint32_t bfr[4][4];
            #pragma unroll
            for (int np = 0; np < 4; np++) {
                #pragma unroll
                for (int wch = 0; wch < 2; wch++) {
                    int n = warp_n * 64 + (np * 2 + wch) * 8 + g;
                    bfr[np][wch * 2 + 0] = __float_as_uint(Bb[(s * 8 + kq) * 260 + n]);
                    bfr[np][wch * 2 + 1] = __float_as_uint(Bb[(s * 8 + kq + 4) * 260 + n]);
                }
            }
            #pragma unroll
            for (int mt = 0; mt < 2; mt++)
                #pragma unroll
                for (int np = 0; np < 4; np++) {
                    mma_tf32(acc[mt][np * 2],     af[mt], bfr[np][0], bfr[np][1]);
                    mma_tf32(acc[mt][np * 2 + 1], af[mt], bfr[np][2], bfr[np][3]);
                }
        }
    };

    load_stage(0); load_stage(1);
    for (int c = 0; c < NCH; c++) {
        if (c + 2 < NCH) {
            load_stage(c + 2);
            asm volatile("cp.async.wait_group 2;" ::: "memory");
        } else {
            asm volatile("cp.async.wait_group 0;" ::: "memory");
        }
        __syncthreads();
        compute(c);
        __syncthreads();
    }

    // ---- epilogue ----
    float temp = 0.f, wT = 0.f, wF = 0.f;
    if (MODE == 2) {
        temp = *temp_p;
        wT = temp / (temp + 1.0f);
        wF = 1.0f / (temp + 1.0f);
    }
    #pragma unroll
    for (int mt = 0; mt < 2; mt++) {
        int rbase = m0 + (warp_m * 2 + mt) * 16 + g;
        #pragma unroll
        for (int half = 0; half < 2; half++) {
            int r = rbase + half * 8;
            if (MODE != 3 && r >= NROWS) continue;
            if (MODE == 2) {
                unsigned rl = (unsigned)r % LL;
                unsigned b  = (unsigned)r / LL;
                size_t dstb = (size_t)b * PLSZP;
                #pragma unroll
                for (int nt = 0; nt < 8; nt++) {
                    int j = n0 + warp_n * 64 + nt * 8 + kq * 2;
                    #pragma unroll
                    for (int e = 0; e < 2; e++) {
                        unsigned rem = rl * 256u + (unsigned)(j + e);
                        unsigned p = rem / LL;
                        unsigned l = rem - p * LL;
                        unsigned lm = l % OHW;
                        unsigned ki = (p >> 1) & 1u, kj = p & 1u;
                        bool masked = (ki == 0u && l < OHW) || (ki == 1u && l >= 3192u) ||
                                      (kj == 0u && lm == 0u) || (kj == 1u && lm == 56u);
                        float av = acc[mt][nt][half * 2 + e];
                        float val = masked ? 0.0f
                            : fmaf(wT, av, wF * g_cols[(size_t)r * 256 + j + e]);
                        g_finalP[dstb + (size_t)p * LLP + l] = tf32r(val);
                    }
                }
            } else if (MODE == 1) {
                #pragma unroll
                for (int nt = 0; nt < 8; nt++) {
                    int col = n0 + warp_n * 64 + nt * 8 + kq * 2;
                    float2 v = make_float2(acc[mt][nt][half * 2], acc[mt][nt][half * 2 + 1]);
                    *(float2*)&g_S[(size_t)r * 512 + col] = v;
                }
            } else {
                float bs = bias[r];
                #pragma unroll
                for (int nt = 0; nt < 8; nt++) {
                    int l = n0 + warp_n * 64 + nt * 8 + kq * 2;
                    #pragma unroll
                    for (int e = 0; e < 2; e++) {
                        if (l + e < LL)
                            out[((size_t)bb * 128 + r) * LL + l + e] =
                                acc[mt][nt][half * 2 + e] + bs;
                    }
                }
            }
        }
    }
}

// ---------------- kernel 4: softmax over 512 centers per row ----------------
__global__ void k_softmax(const float* __restrict__ temp_p) {
    __shared__ float c2s[KCL];
    for (int i = threadIdx.x; i < KCL; i += 256) c2s[i] = g_c2[i];
    __syncthreads();
    int n = blockIdx.x * 8 + (threadIdx.x >> 5);
    int lane = threadIdx.x & 31;
    float temp = *temp_p;
    float x2 = g_x2[n];
    float sc[16];
    float m = -1e30f;
    #pragma unroll
    for (int i = 0; i < 16; i++) {
        int k = lane + 32 * i;
        float s = g_S[(size_t)n * 512 + k];
        float q = fmaxf(fmaf(-2.0f, s, x2 + c2s[k]), 0.0f);
        sc[i] = -fast_sqrtf(q) * temp;
        m = fmaxf(m, sc[i]);
    }
    #pragma unroll
    for (int o = 16; o; o >>= 1) m = fmaxf(m, __shfl_xor_sync(0xffffffffu, m, o));
    float e[16];
    float sum = 0.0f;
    #pragma unroll
    for (int i = 0; i < 16; i++) { e[i] = fast_expf(sc[i] - m); sum += e[i]; }
    #pragma unroll
    for (int o = 16; o; o >>= 1) sum += __shfl_xor_sync(0xffffffffu, sum, o);
    float inv = 1.0f / sum;
    #pragma unroll
    for (int i = 0; i < 16; i++)
        g_S[(size_t)n * 512 + lane + 32 * i] = tf32r(e[i] * inv);
}

// ---------------- launcher ----------------
extern "C" void kernel_launch(void* const* d_in, const int* in_sizes, int n_in,
                              void* d_out, int out_size) {
    const float* x    = (const float*)d_in[0];
    const float* w    = (const float*)d_in[1];
    const float* bias = (const float*)d_in[2];
    const float* cent = (const float*)d_in[3];
    const float* temp = (const float*)d_in[4];
    float* out = (float*)d_out;

    const int SM_BYTES = 3 * (128 * 32 + 32 * 260) * 4;   // 148992
    cudaFuncSetAttribute(k_mma<256, 1>, cudaFuncAttributeMaxDynamicSharedMemorySize, SM_BYTES);
    cudaFuncSetAttribute(k_mma<512, 2>, cudaFuncAttributeMaxDynamicSharedMemorySize, SM_BYTES);
    cudaFuncSetAttribute(k_mma<256, 3>, cudaFuncAttributeMaxDynamicSharedMemorySize, SM_BYTES);

    k_unfold<<<12996, 256>>>(x);
    k_c2<<<64, 256>>>(cent);
    k_tr<<<dim3(16, 8), 256>>>(cent);
    k_rw<<<128, 256>>>(w);
    k_mma<256, 1><<<dim3(2, 813), 512, SM_BYTES>>>(temp, bias, out);
    k_softmax<<<12996, 256>>>(temp);
    k_mma<512, 2><<<dim3(1, 813), 512, SM_BYTES>>>(temp, bias, out);
    k_mma<256, 3><<<dim3(13, 32), 512, SM_BYTES>>>(temp, bias, out);
}